// round 1
// baseline (speedup 1.0000x reference)
#include <cuda_runtime.h>
#include <cuda_bf16.h>
#include <math.h>

// Problem constants (match reference; runtime values derived from in_sizes)
#define NMAX 50000
#define EMAX 800000
#define HID  128
#define CO   40

// ---------------- scratch (device globals; no allocation allowed) ----------
__device__ __align__(16) float g_bufA[NMAX * HID];
__device__ __align__(16) float g_bufB[NMAX * HID];
__device__ __align__(16) float g_h3[NMAX * CO];
__device__ __align__(16) float g_agg3[NMAX * CO];
__device__ __align__(16) float g_dinv[NMAX];
__device__ __align__(16) float g_stats[2 * HID];   // sums, sumsq
__device__ __align__(16) float g_coef[2 * HID];    // scale, shift

// ---------------- degree / norm ----------------
__global__ void deg_init(int n) {
    int i = blockIdx.x * blockDim.x + threadIdx.x;
    if (i < n) g_dinv[i] = 1.0f;  // self loop
}
__global__ void deg_count(const int* __restrict__ ei, int e) {
    int i = blockIdx.x * blockDim.x + threadIdx.x;
    if (i < e) atomicAdd(&g_dinv[ei[e + i]], 1.0f);  // dst = ei[E + i]
}
__global__ void deg_finish(int n) {
    int i = blockIdx.x * blockDim.x + threadIdx.x;
    if (i < n) g_dinv[i] = rsqrtf(g_dinv[i]);
}

// ---------------- SGEMM: C[M x 128] = A[M x 128] * W[128 x 128] ------------
// BM=64, BN=128, BK=16, 256 threads, 8x4 per thread.
__global__ void gemm128_kernel(const float* __restrict__ A,
                               const float* __restrict__ W,
                               float* __restrict__ C, int M) {
    __shared__ float As[16][65];
    __shared__ float Bs[16][128];
    const int tid = threadIdx.x;
    const int tx = tid & 31;        // 32 col groups of 4
    const int ty = tid >> 5;        // 8 row groups of 8
    const int row0 = blockIdx.x * 64;

    float acc[8][4];
#pragma unroll
    for (int i = 0; i < 8; i++)
#pragma unroll
        for (int j = 0; j < 4; j++) acc[i][j] = 0.0f;

    const int am = tid >> 2;              // 0..63
    const int ak = (tid & 3) << 2;        // 0,4,8,12

    for (int kk = 0; kk < 128; kk += 16) {
        // A tile: 64 x 16, one float4 per thread
        float4 av = make_float4(0.f, 0.f, 0.f, 0.f);
        int gr = row0 + am;
        if (gr < M) av = *(const float4*)(A + (size_t)gr * 128 + kk + ak);
        As[ak + 0][am] = av.x;
        As[ak + 1][am] = av.y;
        As[ak + 2][am] = av.z;
        As[ak + 3][am] = av.w;
        // B tile: 16 x 128, two float4 per thread
#pragma unroll
        for (int i = 0; i < 2; i++) {
            int v = tid + i * 256;
            int br = v >> 5, bc = (v & 31) << 2;
            *(float4*)&Bs[br][bc] = *(const float4*)(W + (size_t)(kk + br) * 128 + bc);
        }
        __syncthreads();
#pragma unroll
        for (int k = 0; k < 16; k++) {
            float ar[8];
#pragma unroll
            for (int i = 0; i < 8; i++) ar[i] = As[k][(ty << 3) + i];
            float4 bv = *(float4*)&Bs[k][tx << 2];
#pragma unroll
            for (int i = 0; i < 8; i++) {
                acc[i][0] = fmaf(ar[i], bv.x, acc[i][0]);
                acc[i][1] = fmaf(ar[i], bv.y, acc[i][1]);
                acc[i][2] = fmaf(ar[i], bv.z, acc[i][2]);
                acc[i][3] = fmaf(ar[i], bv.w, acc[i][3]);
            }
        }
        __syncthreads();
    }
#pragma unroll
    for (int i = 0; i < 8; i++) {
        int gr = row0 + (ty << 3) + i;
        if (gr < M)
            ((float4*)(C + (size_t)gr * 128))[tx] =
                make_float4(acc[i][0], acc[i][1], acc[i][2], acc[i][3]);
    }
}

// ---------------- SGEMM: C[M x 40] = A[M x 128] * W[128 x 40] --------------
// 32 rows per block, 256 threads, 5 cols per thread.
__global__ void gemm40_kernel(const float* __restrict__ A,
                              const float* __restrict__ W,
                              float* __restrict__ C, int M) {
    __shared__ float Xs[32][133];
    __shared__ float Ws[128 * 40];
    const int tid = threadIdx.x;
    const int row0 = blockIdx.x * 32;

    for (int i = tid; i < 128 * 40; i += 256) Ws[i] = W[i];
#pragma unroll
    for (int i = 0; i < 4; i++) {
        int v = tid + i * 256;       // 0..1023
        int r = v >> 5, c = (v & 31) << 2;
        float4 xv = make_float4(0.f, 0.f, 0.f, 0.f);
        int gr = row0 + r;
        if (gr < M) xv = *(const float4*)(A + (size_t)gr * 128 + c);
        Xs[r][c + 0] = xv.x; Xs[r][c + 1] = xv.y;
        Xs[r][c + 2] = xv.z; Xs[r][c + 3] = xv.w;
    }
    __syncthreads();

    const int r = tid >> 3;      // 0..31
    const int cg = tid & 7;      // 8 groups of 5 cols
    float acc[5] = {0.f, 0.f, 0.f, 0.f, 0.f};
#pragma unroll 8
    for (int k = 0; k < 128; k++) {
        float xv = Xs[r][k];
        const float* wr = &Ws[k * 40 + cg * 5];
#pragma unroll
        for (int c = 0; c < 5; c++) acc[c] = fmaf(xv, wr[c], acc[c]);
    }
    int gr = row0 + r;
    if (gr < M) {
        float* out = C + (size_t)gr * 40 + cg * 5;
#pragma unroll
        for (int c = 0; c < 5; c++) out[c] = acc[c];
    }
}

// ---------------- aggregation ----------------
// Init AGG with self-loop contribution: AGG[i,:] = H[i,:] * dinv[i]^2
__global__ void self_init128(const float* __restrict__ H, float* __restrict__ Agg,
                             int total4) {
    int i = blockIdx.x * blockDim.x + threadIdx.x;
    if (i >= total4) return;
    int row = i >> 5;
    float di = g_dinv[row];
    float c = di * di;
    float4 v = ((const float4*)H)[i];
    ((float4*)Agg)[i] = make_float4(v.x * c, v.y * c, v.z * c, v.w * c);
}
__global__ void self_init40(const float* __restrict__ H, float* __restrict__ Agg,
                            int total4) {
    int i = blockIdx.x * blockDim.x + threadIdx.x;
    if (i >= total4) return;
    int row = i / 10;  // 10 float4 per row of 40
    float di = g_dinv[row];
    float c = di * di;
    float4 v = ((const float4*)H)[i];
    ((float4*)Agg)[i] = make_float4(v.x * c, v.y * c, v.z * c, v.w * c);
}

__device__ __forceinline__ void atomic_add_f4(float4* p, float4 v) {
#if __CUDA_ARCH__ >= 900
    atomicAdd(p, v);
#else
    atomicAdd(&p->x, v.x); atomicAdd(&p->y, v.y);
    atomicAdd(&p->z, v.z); atomicAdd(&p->w, v.w);
#endif
}

// One warp per edge (grid-strided): gather H[src], scale, vector-atomic into AGG[dst]
__global__ void agg_edges128(const int* __restrict__ ei,
                             const float* __restrict__ H,
                             float* __restrict__ Agg, int e) {
    int lane = threadIdx.x & 31;
    int warp = (blockIdx.x * blockDim.x + threadIdx.x) >> 5;
    int nwarps = (gridDim.x * blockDim.x) >> 5;
    for (int ed = warp; ed < e; ed += nwarps) {
        int s = ei[ed];
        int d = ei[e + ed];
        float c = g_dinv[s] * g_dinv[d];
        float4 v = ((const float4*)(H + (size_t)s * 128))[lane];
        atomic_add_f4(((float4*)(Agg + (size_t)d * 128)) + lane,
                      make_float4(v.x * c, v.y * c, v.z * c, v.w * c));
    }
}

__global__ void agg_edges40(const int* __restrict__ ei,
                            const float* __restrict__ H,
                            float* __restrict__ Agg, int e) {
    int lane = threadIdx.x & 31;
    int warp = (blockIdx.x * blockDim.x + threadIdx.x) >> 5;
    int nwarps = (gridDim.x * blockDim.x) >> 5;
    for (int ed = warp; ed < e; ed += nwarps) {
        int s = ei[ed];
        int d = ei[e + ed];
        float c = g_dinv[s] * g_dinv[d];
        if (lane < 10) {
            float4 v = ((const float4*)(H + (size_t)s * 40))[lane];
            atomic_add_f4(((float4*)(Agg + (size_t)d * 40)) + lane,
                          make_float4(v.x * c, v.y * c, v.z * c, v.w * c));
        }
    }
}

// ---------------- BatchNorm ----------------
__global__ void zero_stats() {
    int i = threadIdx.x;
    if (i < 256) g_stats[i] = 0.0f;
}
__global__ void bn_stats(const float* __restrict__ A, int M) {
    int f = threadIdx.x;  // 128 threads, one column each
    float s = 0.f, s2 = 0.f;
    for (int r = blockIdx.x; r < M; r += gridDim.x) {
        float x = A[(size_t)r * 128 + f];
        s += x;
        s2 += x * x;
    }
    atomicAdd(&g_stats[f], s);
    atomicAdd(&g_stats[128 + f], s2);
}
__global__ void bn_coef(const float* __restrict__ gamma,
                        const float* __restrict__ beta, float invM) {
    int f = threadIdx.x;
    float mu = g_stats[f] * invM;
    float var = g_stats[128 + f] * invM - mu * mu;
    float scl = gamma[f] * rsqrtf(var + 1e-5f);
    g_coef[f] = scl;
    g_coef[128 + f] = beta[f] - mu * scl;
}
__global__ void bn_apply_relu(const float* __restrict__ A, float* __restrict__ Y,
                              int total4) {
    int i = blockIdx.x * blockDim.x + threadIdx.x;
    if (i >= total4) return;
    int c4 = i & 31;
    float4 x = ((const float4*)A)[i];
    float4 s = ((const float4*)g_coef)[c4];
    float4 t = ((const float4*)g_coef)[32 + c4];
    float4 y;
    y.x = fmaxf(fmaf(x.x, s.x, t.x), 0.f);
    y.y = fmaxf(fmaf(x.y, s.y, t.y), 0.f);
    y.z = fmaxf(fmaf(x.z, s.z, t.z), 0.f);
    y.w = fmaxf(fmaf(x.w, s.w, t.w), 0.f);
    ((float4*)Y)[i] = y;
}

// ---------------- log-softmax (40 classes), one warp per row ---------------
__global__ void logsm_kernel(const float* __restrict__ A,
                             const float* __restrict__ b3,
                             float* __restrict__ out, int M) {
    int lane = threadIdx.x & 31;
    int row = (blockIdx.x * blockDim.x + threadIdx.x) >> 5;
    if (row >= M) return;
    const float* x = A + (size_t)row * 40;
    float v0 = x[lane] + b3[lane];
    float v1 = (lane < 8) ? x[32 + lane] + b3[32 + lane] : -3.0e38f;
    float mx = fmaxf(v0, v1);
#pragma unroll
    for (int o = 16; o; o >>= 1) mx = fmaxf(mx, __shfl_xor_sync(0xffffffffu, mx, o));
    float se = expf(v0 - mx) + ((lane < 8) ? expf(v1 - mx) : 0.f);
#pragma unroll
    for (int o = 16; o; o >>= 1) se += __shfl_xor_sync(0xffffffffu, se, o);
    float lse = logf(se);
    out[(size_t)row * 40 + lane] = v0 - mx - lse;
    if (lane < 8) out[(size_t)row * 40 + 32 + lane] = v1 - mx - lse;
}

// ---------------- launch ----------------
extern "C" void kernel_launch(void* const* d_in, const int* in_sizes, int n_in,
                              void* d_out, int out_size) {
    const float* feats = (const float*)d_in[0];
    const int*   ei    = (const int*)d_in[1];
    const float* W1 = (const float*)d_in[2];
    const float* g1 = (const float*)d_in[4];
    const float* be1 = (const float*)d_in[5];
    const float* W2 = (const float*)d_in[6];
    const float* g2 = (const float*)d_in[8];
    const float* be2 = (const float*)d_in[9];
    const float* W3 = (const float*)d_in[10];
    const float* b3 = (const float*)d_in[11];
    float* out = (float*)d_out;

    const int Nn = in_sizes[0] / HID;
    const int Ee = in_sizes[1] / 2;

    float *bufA, *bufB, *h3, *agg3;
    cudaGetSymbolAddress((void**)&bufA, g_bufA);
    cudaGetSymbolAddress((void**)&bufB, g_bufB);
    cudaGetSymbolAddress((void**)&h3, g_h3);
    cudaGetSymbolAddress((void**)&agg3, g_agg3);

    const int total4 = Nn * HID / 4;     // 1.6M float4
    const int total4_40 = Nn * CO / 4;
    const float invM = 1.0f / (float)Nn;

    const int AGG_GRID = 4096;           // grid-strided warp-per-edge

    // degree + dinv
    deg_init<<<(Nn + 255) / 256, 256>>>(Nn);
    deg_count<<<(Ee + 255) / 256, 256>>>(ei, Ee);
    deg_finish<<<(Nn + 255) / 256, 256>>>(Nn);

    // ---- layer 1 ----
    gemm128_kernel<<<(Nn + 63) / 64, 256>>>(feats, W1, bufA, Nn);
    self_init128<<<(total4 + 255) / 256, 256>>>(bufA, bufB, total4);
    agg_edges128<<<AGG_GRID, 256>>>(ei, bufA, bufB, Ee);
    zero_stats<<<1, 256>>>();
    bn_stats<<<512, 128>>>(bufB, Nn);
    bn_coef<<<1, 128>>>(g1, be1, invM);
    bn_apply_relu<<<(total4 + 255) / 256, 256>>>(bufB, bufA, total4);

    // ---- layer 2 ----
    gemm128_kernel<<<(Nn + 63) / 64, 256>>>(bufA, W2, bufB, Nn);
    self_init128<<<(total4 + 255) / 256, 256>>>(bufB, bufA, total4);
    agg_edges128<<<AGG_GRID, 256>>>(ei, bufB, bufA, Ee);
    zero_stats<<<1, 256>>>();
    bn_stats<<<512, 128>>>(bufA, Nn);
    bn_coef<<<1, 128>>>(g2, be2, invM);
    bn_apply_relu<<<(total4 + 255) / 256, 256>>>(bufA, bufB, total4);

    // ---- layer 3 ----
    gemm40_kernel<<<(Nn + 31) / 32, 256>>>(bufB, W3, h3, Nn);
    self_init40<<<(total4_40 + 255) / 256, 256>>>(h3, agg3, total4_40);
    agg_edges40<<<AGG_GRID, 256>>>(ei, h3, agg3, Ee);
    logsm_kernel<<<(Nn * 32 + 255) / 256, 256>>>(agg3, b3, out, Nn);
}

// round 3
// speedup vs baseline: 1.3847x; 1.3847x over previous
#include <cuda_runtime.h>
#include <cuda_bf16.h>
#include <math.h>

#define NMAX 50000
#define EMAX 800000
#define HID  128
#define CO   40

// ---------------- scratch (device globals) ----------------
__device__ __align__(16) float g_bufA[NMAX * HID];
__device__ __align__(16) float g_bufB[NMAX * HID];
__device__ __align__(16) float g_h3[NMAX * CO];
__device__ __align__(16) float g_agg3[NMAX * CO];
__device__ __align__(16) float g_dinv[NMAX];
__device__ int   g_cnt[NMAX];                 // degree counts (incl self)
__device__ int   g_off[NMAX + 1];             // CSR offsets
__device__ int   g_cur[NMAX];                 // scatter cursors
__device__ int   g_bsum[128];                 // scan block sums
__device__ int   g_csr_src[EMAX + NMAX];
__device__ float g_csr_coef[EMAX + NMAX];
__device__ __align__(16) float g_stats[2 * HID];
__device__ __align__(16) float g_coef[2 * HID];

// ---------------- degree ----------------
__global__ void deg_init(int n) {
    int i = blockIdx.x * blockDim.x + threadIdx.x;
    if (i < n) g_cnt[i] = 1;  // self loop
}
__global__ void deg_count(const int* __restrict__ ei, int e) {
    int i = blockIdx.x * blockDim.x + threadIdx.x;
    if (i < e) atomicAdd(&g_cnt[ei[e + i]], 1);
}
__global__ void deg_finish(int n) {
    int i = blockIdx.x * blockDim.x + threadIdx.x;
    if (i < n) g_dinv[i] = rsqrtf((float)g_cnt[i]);
}

// ---------------- exclusive scan of g_cnt -> g_off ----------------
__global__ void scanA(int n) {
    __shared__ int s[1024];
    int i = blockIdx.x * 1024 + threadIdx.x;
    int v = (i < n) ? g_cnt[i] : 0;
    s[threadIdx.x] = v;
    __syncthreads();
#pragma unroll
    for (int off = 1; off < 1024; off <<= 1) {
        int t = (threadIdx.x >= off) ? s[threadIdx.x - off] : 0;
        __syncthreads();
        s[threadIdx.x] += t;
        __syncthreads();
    }
    if (i < n) g_off[i + 1] = s[threadIdx.x];   // inclusive within block
    if (threadIdx.x == 1023) g_bsum[blockIdx.x] = s[1023];
}
__global__ void scanB(int nb) {
    if (threadIdx.x == 0) {
        int run = 0;
        for (int j = 0; j < nb; j++) { int t = g_bsum[j]; g_bsum[j] = run; run += t; }
    }
}
__global__ void scanC(int n) {
    int i = blockIdx.x * 1024 + threadIdx.x;
    if (i < n) {
        int o = g_off[i + 1] + g_bsum[blockIdx.x];
        g_off[i + 1] = o;
    }
    if (i == 0) g_off[0] = 0;
}
__global__ void cur_init(int n) {
    int i = blockIdx.x * blockDim.x + threadIdx.x;
    if (i < n) g_cur[i] = g_off[i];
}
__global__ void scatter_self(int n) {
    int i = blockIdx.x * blockDim.x + threadIdx.x;
    if (i < n) {
        int p = atomicAdd(&g_cur[i], 1);
        float di = g_dinv[i];
        g_csr_src[p] = i;
        g_csr_coef[p] = di * di;
    }
}
__global__ void scatter_edges(const int* __restrict__ ei, int e) {
    int i = blockIdx.x * blockDim.x + threadIdx.x;
    if (i < e) {
        int s = ei[i];
        int d = ei[e + i];
        int p = atomicAdd(&g_cur[d], 1);
        g_csr_src[p] = s;
        g_csr_coef[p] = g_dinv[s] * g_dinv[d];
    }
}

// ---------------- SGEMM 128x128, optional fused BN+ReLU on A ---------------
template <int BN>
__global__ void gemm128_kernel(const float* __restrict__ A,
                               const float* __restrict__ W,
                               float* __restrict__ C, int M) {
    __shared__ float As[16][65];
    __shared__ float Bs[16][128];
    const int tid = threadIdx.x;
    const int tx = tid & 31;
    const int ty = tid >> 5;
    const int row0 = blockIdx.x * 64;

    float acc[8][4];
#pragma unroll
    for (int i = 0; i < 8; i++)
#pragma unroll
        for (int j = 0; j < 4; j++) acc[i][j] = 0.0f;

    const int am = tid >> 2;
    const int ak = (tid & 3) << 2;

    for (int kk = 0; kk < 128; kk += 16) {
        float4 av = make_float4(0.f, 0.f, 0.f, 0.f);
        int gr = row0 + am;
        if (gr < M) av = *(const float4*)(A + (size_t)gr * 128 + kk + ak);
        if (BN) {
            int f4 = (kk + ak) >> 2;
            float4 s = ((const float4*)g_coef)[f4];
            float4 t = ((const float4*)g_coef)[32 + f4];
            av.x = fmaxf(fmaf(av.x, s.x, t.x), 0.f);
            av.y = fmaxf(fmaf(av.y, s.y, t.y), 0.f);
            av.z = fmaxf(fmaf(av.z, s.z, t.z), 0.f);
            av.w = fmaxf(fmaf(av.w, s.w, t.w), 0.f);
        }
        As[ak + 0][am] = av.x;
        As[ak + 1][am] = av.y;
        As[ak + 2][am] = av.z;
        As[ak + 3][am] = av.w;
#pragma unroll
        for (int i = 0; i < 2; i++) {
            int v = tid + i * 256;
            int br = v >> 5, bc = (v & 31) << 2;
            *(float4*)&Bs[br][bc] = *(const float4*)(W + (size_t)(kk + br) * 128 + bc);
        }
        __syncthreads();
#pragma unroll
        for (int k = 0; k < 16; k++) {
            float ar[8];
#pragma unroll
            for (int i = 0; i < 8; i++) ar[i] = As[k][(ty << 3) + i];
            float4 bv = *(float4*)&Bs[k][tx << 2];
#pragma unroll
            for (int i = 0; i < 8; i++) {
                acc[i][0] = fmaf(ar[i], bv.x, acc[i][0]);
                acc[i][1] = fmaf(ar[i], bv.y, acc[i][1]);
                acc[i][2] = fmaf(ar[i], bv.z, acc[i][2]);
                acc[i][3] = fmaf(ar[i], bv.w, acc[i][3]);
            }
        }
        __syncthreads();
    }
#pragma unroll
    for (int i = 0; i < 8; i++) {
        int gr = row0 + (ty << 3) + i;
        if (gr < M)
            ((float4*)(C + (size_t)gr * 128))[tx] =
                make_float4(acc[i][0], acc[i][1], acc[i][2], acc[i][3]);
    }
}

// ---------------- SGEMM 128x40 with fused BN+ReLU on A ---------------------
__global__ void gemm40_kernel(const float* __restrict__ A,
                              const float* __restrict__ W,
                              float* __restrict__ C, int M) {
    __shared__ float Xs[32][133];
    __shared__ float Ws[128 * 40];
    const int tid = threadIdx.x;
    const int row0 = blockIdx.x * 32;

    for (int i = tid; i < 128 * 40; i += 256) Ws[i] = W[i];
#pragma unroll
    for (int i = 0; i < 4; i++) {
        int v = tid + i * 256;
        int r = v >> 5, c = (v & 31) << 2;
        float4 xv = make_float4(0.f, 0.f, 0.f, 0.f);
        int gr = row0 + r;
        if (gr < M) xv = *(const float4*)(A + (size_t)gr * 128 + c);
        // fused BN2 + relu
        float4 s = ((const float4*)g_coef)[c >> 2];
        float4 t = ((const float4*)g_coef)[32 + (c >> 2)];
        Xs[r][c + 0] = fmaxf(fmaf(xv.x, s.x, t.x), 0.f);
        Xs[r][c + 1] = fmaxf(fmaf(xv.y, s.y, t.y), 0.f);
        Xs[r][c + 2] = fmaxf(fmaf(xv.z, s.z, t.z), 0.f);
        Xs[r][c + 3] = fmaxf(fmaf(xv.w, s.w, t.w), 0.f);
    }
    __syncthreads();

    const int r = tid >> 3;
    const int cg = tid & 7;
    float acc[5] = {0.f, 0.f, 0.f, 0.f, 0.f};
#pragma unroll 8
    for (int k = 0; k < 128; k++) {
        float xv = Xs[r][k];
        const float* wr = &Ws[k * 40 + cg * 5];
#pragma unroll
        for (int c = 0; c < 5; c++) acc[c] = fmaf(xv, wr[c], acc[c]);
    }
    int gr = row0 + r;
    if (gr < M) {
        float* out = C + (size_t)gr * 40 + cg * 5;
#pragma unroll
        for (int c = 0; c < 5; c++) out[c] = acc[c];
    }
}

// ---------------- CSR gather aggregation (no atomics) ----------------------
__global__ void agg_csr128(const float* __restrict__ H,
                           float* __restrict__ Agg, int n) {
    int warp = (blockIdx.x * blockDim.x + threadIdx.x) >> 5;
    int lane = threadIdx.x & 31;
    if (warp >= n) return;
    int beg = g_off[warp], end = g_off[warp + 1];
    float4 acc = make_float4(0.f, 0.f, 0.f, 0.f);
    int e = beg;
    for (; e + 1 < end; e += 2) {
        int   s0 = g_csr_src[e],     s1 = g_csr_src[e + 1];
        float c0 = g_csr_coef[e],    c1 = g_csr_coef[e + 1];
        float4 v0 = ((const float4*)(H + (size_t)s0 * 128))[lane];
        float4 v1 = ((const float4*)(H + (size_t)s1 * 128))[lane];
        acc.x = fmaf(v0.x, c0, fmaf(v1.x, c1, acc.x));
        acc.y = fmaf(v0.y, c0, fmaf(v1.y, c1, acc.y));
        acc.z = fmaf(v0.z, c0, fmaf(v1.z, c1, acc.z));
        acc.w = fmaf(v0.w, c0, fmaf(v1.w, c1, acc.w));
    }
    if (e < end) {
        int s0 = g_csr_src[e];
        float c0 = g_csr_coef[e];
        float4 v0 = ((const float4*)(H + (size_t)s0 * 128))[lane];
        acc.x = fmaf(v0.x, c0, acc.x);
        acc.y = fmaf(v0.y, c0, acc.y);
        acc.z = fmaf(v0.z, c0, acc.z);
        acc.w = fmaf(v0.w, c0, acc.w);
    }
    ((float4*)(Agg + (size_t)warp * 128))[lane] = acc;
}

__global__ void agg_csr40(const float* __restrict__ H,
                          float* __restrict__ Agg, int n) {
    int warp = (blockIdx.x * blockDim.x + threadIdx.x) >> 5;
    int lane = threadIdx.x & 31;
    if (warp >= n) return;
    int beg = g_off[warp], end = g_off[warp + 1];
    float4 acc = make_float4(0.f, 0.f, 0.f, 0.f);
    for (int e = beg; e < end; e++) {
        int s0 = g_csr_src[e];
        float c0 = g_csr_coef[e];
        if (lane < 10) {
            float4 v0 = ((const float4*)(H + (size_t)s0 * 40))[lane];
            acc.x = fmaf(v0.x, c0, acc.x);
            acc.y = fmaf(v0.y, c0, acc.y);
            acc.z = fmaf(v0.z, c0, acc.z);
            acc.w = fmaf(v0.w, c0, acc.w);
        }
    }
    if (lane < 10) ((float4*)(Agg + (size_t)warp * 40))[lane] = acc;
}

// ---------------- BatchNorm stats ----------------
__global__ void zero_stats() {
    int i = threadIdx.x;
    if (i < 256) g_stats[i] = 0.0f;
}
__global__ void bn_stats(const float* __restrict__ A, int M) {
    int f = threadIdx.x;
    float s = 0.f, s2 = 0.f;
    for (int r = blockIdx.x; r < M; r += gridDim.x) {
        float x = A[(size_t)r * 128 + f];
        s += x;
        s2 += x * x;
    }
    atomicAdd(&g_stats[f], s);
    atomicAdd(&g_stats[128 + f], s2);
}
__global__ void bn_coef(const float* __restrict__ gamma,
                        const float* __restrict__ beta, float invM) {
    int f = threadIdx.x;
    float mu = g_stats[f] * invM;
    float var = g_stats[128 + f] * invM - mu * mu;
    float scl = gamma[f] * rsqrtf(var + 1e-5f);
    g_coef[f] = scl;
    g_coef[128 + f] = beta[f] - mu * scl;
}

// ---------------- log-softmax ----------------
__global__ void logsm_kernel(const float* __restrict__ A,
                             const float* __restrict__ b3,
                             float* __restrict__ out, int M) {
    int lane = threadIdx.x & 31;
    int row = (blockIdx.x * blockDim.x + threadIdx.x) >> 5;
    if (row >= M) return;
    const float* x = A + (size_t)row * 40;
    float v0 = x[lane] + b3[lane];
    float v1 = (lane < 8) ? x[32 + lane] + b3[32 + lane] : -3.0e38f;
    float mx = fmaxf(v0, v1);
#pragma unroll
    for (int o = 16; o; o >>= 1) mx = fmaxf(mx, __shfl_xor_sync(0xffffffffu, mx, o));
    float se = expf(v0 - mx) + ((lane < 8) ? expf(v1 - mx) : 0.f);
#pragma unroll
    for (int o = 16; o; o >>= 1) se += __shfl_xor_sync(0xffffffffu, se, o);
    float lse = logf(se);
    out[(size_t)row * 40 + lane] = v0 - mx - lse;
    if (lane < 8) out[(size_t)row * 40 + 32 + lane] = v1 - mx - lse;
}

// ---------------- launch ----------------
extern "C" void kernel_launch(void* const* d_in, const int* in_sizes, int n_in,
                              void* d_out, int out_size) {
    const float* feats = (const float*)d_in[0];
    const int*   ei    = (const int*)d_in[1];
    const float* W1 = (const float*)d_in[2];
    const float* g1 = (const float*)d_in[4];
    const float* be1 = (const float*)d_in[5];
    const float* W2 = (const float*)d_in[6];
    const float* g2 = (const float*)d_in[8];
    const float* be2 = (const float*)d_in[9];
    const float* W3 = (const float*)d_in[10];
    const float* b3 = (const float*)d_in[11];
    float* out = (float*)d_out;

    const int Nn = in_sizes[0] / HID;
    const int Ee = in_sizes[1] / 2;

    float *bufA, *bufB, *h3, *agg3;
    cudaGetSymbolAddress((void**)&bufA, g_bufA);
    cudaGetSymbolAddress((void**)&bufB, g_bufB);
    cudaGetSymbolAddress((void**)&h3, g_h3);
    cudaGetSymbolAddress((void**)&agg3, g_agg3);

    const float invM = 1.0f / (float)Nn;
    const int nb = (Nn + 1023) / 1024;
    const int AGG_BLOCKS = (Nn + 7) / 8;       // warp per node, 8 warps/block

    // ---- degree + CSR build (once; reused by all 3 layers) ----
    deg_init<<<(Nn + 255) / 256, 256>>>(Nn);
    deg_count<<<(Ee + 255) / 256, 256>>>(ei, Ee);
    deg_finish<<<(Nn + 255) / 256, 256>>>(Nn);
    scanA<<<nb, 1024>>>(Nn);
    scanB<<<1, 32>>>(nb);
    scanC<<<nb, 1024>>>(Nn);
    cur_init<<<(Nn + 255) / 256, 256>>>(Nn);
    scatter_self<<<(Nn + 255) / 256, 256>>>(Nn);
    scatter_edges<<<(Ee + 255) / 256, 256>>>(ei, Ee);

    // ---- layer 1 ----
    gemm128_kernel<0><<<(Nn + 63) / 64, 256>>>(feats, W1, bufA, Nn);
    agg_csr128<<<AGG_BLOCKS, 256>>>(bufA, bufB, Nn);
    zero_stats<<<1, 256>>>();
    bn_stats<<<512, 128>>>(bufB, Nn);
    bn_coef<<<1, 128>>>(g1, be1, invM);

    // ---- layer 2 (BN1+ReLU fused into A-load) ----
    gemm128_kernel<1><<<(Nn + 63) / 64, 256>>>(bufB, W2, bufA, Nn);
    agg_csr128<<<AGG_BLOCKS, 256>>>(bufA, bufB, Nn);
    zero_stats<<<1, 256>>>();
    bn_stats<<<512, 128>>>(bufB, Nn);
    bn_coef<<<1, 128>>>(g2, be2, invM);

    // ---- layer 3 (BN2+ReLU fused into A-load) ----
    gemm40_kernel<<<(Nn + 31) / 32, 256>>>(bufB, W3, h3, Nn);
    agg_csr40<<<AGG_BLOCKS, 256>>>(h3, agg3, Nn);
    logsm_kernel<<<(Nn * 32 + 255) / 256, 256>>>(agg3, b3, out, Nn);
}